// round 2
// baseline (speedup 1.0000x reference)
#include <cuda_runtime.h>

// Problem constants
#define BSZ 64
#define ICAPS 8192
#define NDIM 8
#define JCAPS 8
#define MDIM 16

#define CI 8                         // in-caps per staged chunk
#define NCHUNKS (ICAPS / CI)         // 1024
#define GRID 148
#define THREADS 512

#define WSTRIDE_J 132                // 128 + 4 pad floats  -> bank-group shift of 4 words per j
#define WSTRIDE_CI (JCAPS * WSTRIDE_J)   // 1056
#define XSTRIDE_B 68                 // 64 + 4 pad floats

// Stage s accumulators: s1, s2, s3 each [B, J, M]
__device__ float g_s[3][BSZ * JCAPS * MDIM];

#define SMEM_FLOATS (CI * WSTRIDE_CI + BSZ * XSTRIDE_B)   // 8448 + 4352 = 12800
#define SMEM_BYTES  (SMEM_FLOATS * 4)                     // 51200 B

typedef unsigned long long u64;

__device__ __forceinline__ u64 pk2(float a, float b) {
    u64 r; asm("mov.b64 %0, {%1, %2};" : "=l"(r) : "f"(a), "f"(b)); return r;
}
__device__ __forceinline__ void upk2(u64 v, float& a, float& b) {
    asm("mov.b64 {%0, %1}, %2;" : "=f"(a), "=f"(b) : "l"(v));
}
__device__ __forceinline__ u64 mul2(u64 a, u64 b) {
    u64 r; asm("mul.rn.f32x2 %0, %1, %2;" : "=l"(r) : "l"(a), "l"(b)); return r;
}
__device__ __forceinline__ void fma2(u64& d, u64 a, u64 b) {
    asm("fma.rn.f32x2 %0, %1, %2, %0;" : "+l"(d) : "l"(a), "l"(b));
}
__device__ __forceinline__ void lds2(u64& a, u64& b, unsigned addr) {
    asm volatile("ld.shared.v2.b64 {%0, %1}, [%2];" : "=l"(a), "=l"(b) : "r"(addr));
}

__global__ __launch_bounds__(THREADS, 1)
void route_kernel(const float* __restrict__ x, const float* __restrict__ W, int stage)
{
    extern __shared__ float sh[];
    float* Ws = sh;
    float* xs = sh + CI * WSTRIDE_CI;

    const int tid  = threadIdx.x;
    const int lane = tid & 31;
    const int w    = tid >> 5;        // warp 0..15
    const int j    = lane & 7;        // out-cap (low 3 bits -> xor 1/2/4 spans j)
    const int bsub = lane >> 3;       // 0..3
    const int b    = w * 4 + bsub;    // this lane's batch (warp covers 4 batches)

    // ---- cumulative v for (b, j): vsum = sum_{st<stage} squash(g_s[st][b,j,:]) ----
    float v[MDIM];
    #pragma unroll
    for (int m = 0; m < MDIM; m++) v[m] = 0.0f;
    for (int st = 0; st < stage; ++st) {
        const float4* sp = reinterpret_cast<const float4*>(&g_s[st][(b * JCAPS + j) * MDIM]);
        float sv[MDIM];
        #pragma unroll
        for (int q = 0; q < 4; q++) {
            const float4 t = sp[q];
            sv[q*4+0] = t.x; sv[q*4+1] = t.y; sv[q*4+2] = t.z; sv[q*4+3] = t.w;
        }
        float sn = 0.0f;
        #pragma unroll
        for (int m = 0; m < MDIM; m++) sn = fmaf(sv[m], sv[m], sn);
        const float scale = sqrtf(sn) / (1.0f + sn);   // == sn/((1+sn)*sqrt(sn))
        #pragma unroll
        for (int m = 0; m < MDIM; m++) v[m] = fmaf(scale, sv[m], v[m]);
    }
    u64 v2[8];
    #pragma unroll
    for (int p = 0; p < 8; p++) v2[p] = pk2(v[2*p], v[2*p+1]);

    u64 sacc2[8];
    #pragma unroll
    for (int p = 0; p < 8; p++) sacc2[p] = 0ull;

    const unsigned ws_base = (unsigned)__cvta_generic_to_shared(Ws);
    const unsigned wlane   = ws_base + (unsigned)(j * WSTRIDE_J) * 4u;

    for (int ch = blockIdx.x; ch < NCHUNKS; ch += GRID) {
        const int i0 = ch * CI;

        __syncthreads();   // previous chunk fully consumed
        // Stage W chunk: global [ci][j][n*16+m] (contiguous 1024/ci) -> Ws[ci][j][128] padded
        #pragma unroll
        for (int t = 0; t < 4; t++) {
            const int idx4 = tid + t * THREADS;        // 2048 float4 total
            const int idx  = idx4 * 4;
            const float4 val = *reinterpret_cast<const float4*>(&W[(size_t)i0 * 1024 + idx]);
            const int ci = idx >> 10;
            const int jj = (idx >> 7) & 7;
            const int k  = idx & 127;
            *reinterpret_cast<float4*>(&Ws[ci * WSTRIDE_CI + jj * WSTRIDE_J + k]) = val;
        }
        // Stage x chunk: x[b, i0..i0+8, :] = 64 contiguous floats per b -> xs[b][64] padded
        #pragma unroll
        for (int t = 0; t < 2; t++) {
            const int idx4 = tid + t * THREADS;        // 1024 float4 total
            const int bb = idx4 >> 4;                  // 16 float4 per batch
            const int k  = (idx4 & 15) * 4;
            *reinterpret_cast<float4*>(&xs[bb * XSTRIDE_B + k]) =
                *reinterpret_cast<const float4*>(&x[(size_t)bb * (ICAPS * NDIM) + (size_t)i0 * NDIM + k]);
        }
        __syncthreads();

        #pragma unroll
        for (int ii = 0; ii < CI; ++ii) {
            // x[b, i, 0..7] (4-way j-broadcast, b rows padded -> conflict-free)
            const float4 xa = *reinterpret_cast<const float4*>(&xs[b * XSTRIDE_B + ii * NDIM]);
            const float4 xb = *reinterpret_cast<const float4*>(&xs[b * XSTRIDE_B + ii * NDIM + 4]);
            u64 xv2[8];
            xv2[0] = pk2(xa.x, xa.x); xv2[1] = pk2(xa.y, xa.y);
            xv2[2] = pk2(xa.z, xa.z); xv2[3] = pk2(xa.w, xa.w);
            xv2[4] = pk2(xb.x, xb.x); xv2[5] = pk2(xb.y, xb.y);
            xv2[6] = pk2(xb.z, xb.z); xv2[7] = pk2(xb.w, xb.w);

            const unsigned wadr = wlane + (unsigned)(ii * WSTRIDE_CI) * 4u;

            // u_hat[b,i,j,0..15] as 8 packed pairs, lane-local
            u64 uh2[8];
            {
                u64 wv0, wv1, wv2_, wv3, wv4, wv5, wv6, wv7;
                lds2(wv0, wv1, wadr);       lds2(wv2_, wv3, wadr + 16);
                lds2(wv4, wv5, wadr + 32);  lds2(wv6, wv7, wadr + 48);
                uh2[0] = mul2(wv0, xv2[0]); uh2[1] = mul2(wv1, xv2[0]);
                uh2[2] = mul2(wv2_, xv2[0]); uh2[3] = mul2(wv3, xv2[0]);
                uh2[4] = mul2(wv4, xv2[0]); uh2[5] = mul2(wv5, xv2[0]);
                uh2[6] = mul2(wv6, xv2[0]); uh2[7] = mul2(wv7, xv2[0]);
            }
            #pragma unroll
            for (int n = 1; n < 8; n++) {
                const unsigned a = wadr + (unsigned)(n * 64);   // n*16 floats
                u64 wv[8];
                lds2(wv[0], wv[1], a);      lds2(wv[2], wv[3], a + 16);
                lds2(wv[4], wv[5], a + 32); lds2(wv[6], wv[7], a + 48);
                #pragma unroll
                for (int p = 0; p < 8; p++) fma2(uh2[p], wv[p], xv2[n]);
            }

            // routing logit: dot(v[b,j,:], u_hat) over 16 m — lane-local
            u64 p2 = mul2(uh2[0], v2[0]);
            #pragma unroll
            for (int p = 1; p < 8; p++) fma2(p2, uh2[p], v2[p]);
            float plo, phi; upk2(p2, plo, phi);
            float pl = plo + phi;

            // softmax over j (xor 1/2/4 within each 8-lane j-group; serves 4 batches at once)
            float mx = pl;
            mx = fmaxf(mx, __shfl_xor_sync(0xffffffffu, mx, 1));
            mx = fmaxf(mx, __shfl_xor_sync(0xffffffffu, mx, 2));
            mx = fmaxf(mx, __shfl_xor_sync(0xffffffffu, mx, 4));
            const float e = __expf(pl - mx);
            float sm = e;
            sm += __shfl_xor_sync(0xffffffffu, sm, 1);
            sm += __shfl_xor_sync(0xffffffffu, sm, 2);
            sm += __shfl_xor_sync(0xffffffffu, sm, 4);
            const float c = __fdividef(e, sm);

            const u64 c2 = pk2(c, c);
            #pragma unroll
            for (int p = 0; p < 8; p++) fma2(sacc2[p], c2, uh2[p]);
        }
    }

    // Flush this warp's disjoint (b, j, :) partial into the stage accumulator
    float* sout = &g_s[stage][0];
    #pragma unroll
    for (int p = 0; p < 8; p++) {
        float lo, hi; upk2(sacc2[p], lo, hi);
        atomicAdd(&sout[(b * JCAPS + j) * MDIM + 2*p    ], lo);
        atomicAdd(&sout[(b * JCAPS + j) * MDIM + 2*p + 1], hi);
    }
}

// out = squash(s3)
__global__ void final_squash_kernel(float* __restrict__ out)
{
    const int t = blockIdx.x * blockDim.x + threadIdx.x;   // 0..511
    const int b = t >> 3;
    const int j = t & 7;
    const float* sp = &g_s[2][(b * JCAPS + j) * MDIM];
    float sv[MDIM];
    float sn = 0.0f;
    #pragma unroll
    for (int m = 0; m < MDIM; m++) { sv[m] = sp[m]; sn = fmaf(sv[m], sv[m], sn); }
    const float scale = sqrtf(sn) / (1.0f + sn);
    #pragma unroll
    for (int m = 0; m < MDIM; m++) out[(b * JCAPS + j) * MDIM + m] = scale * sv[m];
}

extern "C" void kernel_launch(void* const* d_in, const int* in_sizes, int n_in,
                              void* d_out, int out_size)
{
    const float* x = (const float*)d_in[0];
    const float* W = (const float*)d_in[1];
    // Defensive: identify by element count (x: 64*8192*8 = 4194304, W: 8388608)
    if (n_in >= 2 && in_sizes[0] == 8388608 && in_sizes[1] == 4194304) {
        x = (const float*)d_in[1];
        W = (const float*)d_in[0];
    }

    cudaFuncSetAttribute(route_kernel, cudaFuncAttributeMaxDynamicSharedMemorySize, SMEM_BYTES);

    void* sptr = nullptr;
    cudaGetSymbolAddress(&sptr, g_s);
    cudaMemsetAsync(sptr, 0, sizeof(float) * 3 * BSZ * JCAPS * MDIM);

    for (int st = 0; st < 3; ++st) {
        route_kernel<<<GRID, THREADS, SMEM_BYTES>>>(x, W, st);
    }
    final_squash_kernel<<<16, 32>>>((float*)d_out);
}

// round 4
// speedup vs baseline: 1.2955x; 1.2955x over previous
#include <cuda_runtime.h>

#define BSZ 64
#define ICAPS 8192
#define JCAPS 8
#define NDIM 8
#define MDIM 16

#define CI 8
#define NCHUNKS (ICAPS / CI)       /* 1024 */
#define THREADS 512

#define W_FLOATS (CI * 1024)       /* 8192: smem layout [ci][n][j^(n&1)][m16] */
#define X_STRIDE 132               /* duplicated x row: 128 data + 4 pad */
#define X_FLOATS (BSZ * X_STRIDE)  /* 8448 */
#define SMEM_BYTES ((W_FLOATS + X_FLOATS) * 4)   /* 66560 B */

__device__ float g_s[3][BSZ * JCAPS * MDIM];   // stage-wise s accumulators

typedef unsigned long long u64;

__device__ __forceinline__ u64 pk2(float a, float b) {
    u64 r; asm("mov.b64 %0, {%1, %2};" : "=l"(r) : "f"(a), "f"(b)); return r;
}
__device__ __forceinline__ void upk2(u64 v, float& a, float& b) {
    asm("mov.b64 {%0, %1}, %2;" : "=f"(a), "=f"(b) : "l"(v));
}
__device__ __forceinline__ u64 mul2(u64 a, u64 b) {
    u64 r; asm("mul.rn.f32x2 %0, %1, %2;" : "=l"(r) : "l"(a), "l"(b)); return r;
}
__device__ __forceinline__ void fma2(u64& d, u64 a, u64 b) {
    asm("fma.rn.f32x2 %0, %1, %2, %0;" : "+l"(d) : "l"(a), "l"(b));
}
__device__ __forceinline__ void lds2(u64& a, u64& b, unsigned addr) {
    asm volatile("ld.shared.v2.b64 {%0, %1}, [%2];" : "=l"(a), "=l"(b) : "r"(addr));
}

__global__ __launch_bounds__(THREADS, 1)
void route_kernel(const float* __restrict__ x, const float* __restrict__ W, int stage)
{
    extern __shared__ float sh[];
    float* Ws = sh;
    float* xs = sh + W_FLOATS;

    const int tid  = threadIdx.x;
    const int lane = tid & 31;
    const int w    = tid >> 5;
    const int j    = lane >> 2;     // out-cap 0..7  (lane bits 2..4)
    const int mq   = lane & 3;      // m-quad 0..3   (lane bits 0..1)
    const int b0   = w * 4;         // warp owns batches b0..b0+3

    // ---- vsum = sum_{st<stage} squash(g_s[st]) for this lane's (4 batches, j, mq) ----
    u64 vp[4][2];
    #pragma unroll
    for (int bb = 0; bb < 4; bb++) {
        float v0 = 0.f, v1 = 0.f, v2v = 0.f, v3 = 0.f;
        for (int st = 0; st < stage; ++st) {
            const float4 s4 = __ldcg(reinterpret_cast<const float4*>(
                &g_s[st][((b0 + bb) * JCAPS + j) * MDIM + mq * 4]));
            float sq = s4.x * s4.x;
            sq = fmaf(s4.y, s4.y, sq);
            sq = fmaf(s4.z, s4.z, sq);
            sq = fmaf(s4.w, s4.w, sq);
            sq += __shfl_xor_sync(0xffffffffu, sq, 1);
            sq += __shfl_xor_sync(0xffffffffu, sq, 2);   // norm^2 over all 16 m
            const float sc = sqrtf(sq) / (1.0f + sq);    // squash scale
            v0 = fmaf(sc, s4.x, v0); v1 = fmaf(sc, s4.y, v1);
            v2v = fmaf(sc, s4.z, v2v); v3 = fmaf(sc, s4.w, v3);
        }
        vp[bb][0] = pk2(v0, v1);
        vp[bb][1] = pk2(v2v, v3);
    }

    u64 sacc[4][2];
    #pragma unroll
    for (int bb = 0; bb < 4; bb++) { sacc[bb][0] = 0ull; sacc[bb][1] = 0ull; }

    const unsigned shbase = (unsigned)__cvta_generic_to_shared(sh);
    const unsigned xsbase = shbase + W_FLOATS * 4u;
    const unsigned we = shbase + (unsigned)((j * 16) + mq * 4) * 4u;        // even n
    const unsigned wo = shbase + (unsigned)(((j ^ 1) * 16) + mq * 4) * 4u;  // odd n (XOR swizzle)

    // ---- register-pipelined chunk loop ----
    int ch = blockIdx.x;            // always < NCHUNKS (grid <= 512)
    float4 wreg[4], xreg[2];
    {
        const float* src = W + (size_t)ch * W_FLOATS;
        #pragma unroll
        for (int q = 0; q < 4; q++)
            wreg[q] = __ldcg(reinterpret_cast<const float4*>(src + (tid + q * THREADS) * 4));
        #pragma unroll
        for (int q = 0; q < 2; q++) {
            const int idx4 = tid + q * THREADS;
            const int b = idx4 >> 4;
            const int k = (idx4 & 15) * 4;
            xreg[q] = __ldcg(reinterpret_cast<const float4*>(
                &x[(size_t)b * (ICAPS * NDIM) + (size_t)ch * (CI * NDIM) + k]));
        }
    }

    while (true) {
        __syncthreads();   // previous chunk fully consumed before overwrite
        // Store W regs with transpose+swizzle: global [ci][j][n][m] -> smem [ci][n][j^(n&1)][m]
        #pragma unroll
        for (int q = 0; q < 4; q++) {
            const int idx = (tid + q * THREADS) * 4;
            const int ci = idx >> 10;
            const int r  = idx & 1023;
            const int jj = r >> 7;
            const int n  = (r >> 4) & 7;
            const int m  = r & 15;
            *reinterpret_cast<float4*>(&Ws[(ci << 10) + (n << 7) + ((jj ^ (n & 1)) << 4) + m]) = wreg[q];
        }
        // Store x regs duplicated
        #pragma unroll
        for (int q = 0; q < 2; q++) {
            const int idx4 = tid + q * THREADS;
            const int b = idx4 >> 4;
            const int k = (idx4 & 15) * 4;
            float* d = xs + b * X_STRIDE + 2 * k;
            *reinterpret_cast<float4*>(d)     = make_float4(xreg[q].x, xreg[q].x, xreg[q].y, xreg[q].y);
            *reinterpret_cast<float4*>(d + 4) = make_float4(xreg[q].z, xreg[q].z, xreg[q].w, xreg[q].w);
        }
        __syncthreads();

        const int chn = ch + (int)gridDim.x;
        const bool have_next = (chn < NCHUNKS);
        if (have_next) {   // preload next chunk; latency hidden under compute
            const float* src = W + (size_t)chn * W_FLOATS;
            #pragma unroll
            for (int q = 0; q < 4; q++)
                wreg[q] = __ldcg(reinterpret_cast<const float4*>(src + (tid + q * THREADS) * 4));
            #pragma unroll
            for (int q = 0; q < 2; q++) {
                const int idx4 = tid + q * THREADS;
                const int b = idx4 >> 4;
                const int k = (idx4 & 15) * 4;
                xreg[q] = __ldcg(reinterpret_cast<const float4*>(
                    &x[(size_t)b * (ICAPS * NDIM) + (size_t)chn * (CI * NDIM) + k]));
            }
        }

        // ---- compute this chunk ----
        #pragma unroll 1
        for (int ii = 0; ii < CI; ++ii) {
            u64 wp[8][2];
            #pragma unroll
            for (int n = 0; n < 8; n++) {
                const unsigned a = ((n & 1) ? wo : we) + (unsigned)(ii * 4096 + n * 512);
                lds2(wp[n][0], wp[n][1], a);
            }
            #pragma unroll
            for (int bb = 0; bb < 4; bb++) {
                const unsigned xa = xsbase + (unsigned)((b0 + bb) * X_STRIDE + ii * 16) * 4u;
                u64 xq[8];
                lds2(xq[0], xq[1], xa);          // broadcast: all lanes same addr
                lds2(xq[2], xq[3], xa + 16);
                lds2(xq[4], xq[5], xa + 32);
                lds2(xq[6], xq[7], xa + 48);

                u64 uh0 = mul2(wp[0][0], xq[0]);
                u64 uh1 = mul2(wp[0][1], xq[0]);
                #pragma unroll
                for (int n = 1; n < 8; n++) {
                    fma2(uh0, wp[n][0], xq[n]);
                    fma2(uh1, wp[n][1], xq[n]);
                }
                // logit = dot(vsum, u_hat) over 16 m  (|logit| < 1 -> no max subtraction)
                u64 pp = mul2(uh0, vp[bb][0]);
                fma2(pp, uh1, vp[bb][1]);
                float plo, phi; upk2(pp, plo, phi);
                float pl = plo + phi;
                pl += __shfl_xor_sync(0xffffffffu, pl, 1);
                pl += __shfl_xor_sync(0xffffffffu, pl, 2);
                const float e = __expf(pl);
                float sm = e;
                sm += __shfl_xor_sync(0xffffffffu, sm, 4);
                sm += __shfl_xor_sync(0xffffffffu, sm, 8);
                sm += __shfl_xor_sync(0xffffffffu, sm, 16);
                const float c = __fdividef(e, sm);
                const u64 c2 = pk2(c, c);
                fma2(sacc[bb][0], c2, uh0);
                fma2(sacc[bb][1], c2, uh1);
            }
        }

        if (!have_next) break;
        ch = chn;
    }

    // ---- flush this warp's disjoint (b, j, mq) partials ----
    float* sout = &g_s[stage][0];
    #pragma unroll
    for (int bb = 0; bb < 4; bb++) {
        const int base = ((b0 + bb) * JCAPS + j) * MDIM + mq * 4;
        float a0, a1, a2, a3;
        upk2(sacc[bb][0], a0, a1);
        upk2(sacc[bb][1], a2, a3);
        atomicAdd(&sout[base + 0], a0);
        atomicAdd(&sout[base + 1], a1);
        atomicAdd(&sout[base + 2], a2);
        atomicAdd(&sout[base + 3], a3);
    }
}

// out = squash(s3)
__global__ void final_squash_kernel(float* __restrict__ out)
{
    const int t = blockIdx.x * blockDim.x + threadIdx.x;   // 0..511
    const int b = t >> 3;
    const int j = t & 7;
    const float* sp = &g_s[2][(b * JCAPS + j) * MDIM];
    float sv[MDIM];
    float sn = 0.0f;
    #pragma unroll
    for (int q = 0; q < 4; q++) {
        const float4 tt = __ldcg(reinterpret_cast<const float4*>(sp + q * 4));
        sv[q*4+0] = tt.x; sv[q*4+1] = tt.y; sv[q*4+2] = tt.z; sv[q*4+3] = tt.w;
    }
    #pragma unroll
    for (int m = 0; m < MDIM; m++) sn = fmaf(sv[m], sv[m], sn);
    const float scale = sqrtf(sn) / (1.0f + sn);
    #pragma unroll
    for (int m = 0; m < MDIM; m++) out[(b * JCAPS + j) * MDIM + m] = scale * sv[m];
}

extern "C" void kernel_launch(void* const* d_in, const int* in_sizes, int n_in,
                              void* d_out, int out_size)
{
    const float* x = (const float*)d_in[0];
    const float* W = (const float*)d_in[1];
    if (n_in >= 2 && in_sizes[0] == 8388608 && in_sizes[1] == 4194304) {
        x = (const float*)d_in[1];
        W = (const float*)d_in[0];
    }

    int dev = 0;
    cudaGetDevice(&dev);
    int sm = 148;
    cudaDeviceGetAttribute(&sm, cudaDevAttrMultiProcessorCount, dev);
    if (sm < 1) sm = 1;
    if (sm > 512) sm = 512;

    cudaFuncSetAttribute(route_kernel, cudaFuncAttributeMaxDynamicSharedMemorySize, SMEM_BYTES);

    void* sptr = nullptr;
    cudaGetSymbolAddress(&sptr, g_s);
    cudaMemsetAsync(sptr, 0, sizeof(float) * 3 * BSZ * JCAPS * MDIM);

    for (int st = 0; st < 3; ++st) {
        route_kernel<<<sm, THREADS, SMEM_BYTES>>>(x, W, st);
    }
    final_squash_kernel<<<16, 32>>>((float*)d_out);
}

// round 5
// speedup vs baseline: 1.5000x; 1.1578x over previous
#include <cuda_runtime.h>

#define BSZ 64
#define ICAPS 8192
#define JCAPS 8
#define NDIM 8
#define MDIM 16

#define CI 8
#define NCHUNKS (ICAPS / CI)       /* 1024 */
#define THREADS 512

#define W_FLOATS (CI * 1024)       /* 8192 per buffer: [ci][n][j^(n&1)][m16] */
#define X_STRIDE 132               /* duplicated x row: 128 data + 4 pad */
#define X_FLOATS (BSZ * X_STRIDE)  /* 8448 */
#define SMEM_FLOATS (2 * W_FLOATS + X_FLOATS)       /* 24832 */
#define SMEM_BYTES (SMEM_FLOATS * 4)                /* 99328 B -> 1 CTA/SM */

__device__ float g_s[3][BSZ * JCAPS * MDIM];   // stage-wise s accumulators

typedef unsigned long long u64;

__device__ __forceinline__ u64 pk2(float a, float b) {
    u64 r; asm("mov.b64 %0, {%1, %2};" : "=l"(r) : "f"(a), "f"(b)); return r;
}
__device__ __forceinline__ void upk2(u64 v, float& a, float& b) {
    asm("mov.b64 {%0, %1}, %2;" : "=f"(a), "=f"(b) : "l"(v));
}
__device__ __forceinline__ u64 mul2(u64 a, u64 b) {
    u64 r; asm("mul.rn.f32x2 %0, %1, %2;" : "=l"(r) : "l"(a), "l"(b)); return r;
}
__device__ __forceinline__ void fma2(u64& d, u64 a, u64 b) {
    asm("fma.rn.f32x2 %0, %1, %2, %0;" : "+l"(d) : "l"(a), "l"(b));
}
__device__ __forceinline__ void lds2(u64& a, u64& b, unsigned addr) {
    asm volatile("ld.shared.v2.b64 {%0, %1}, [%2];" : "=l"(a), "=l"(b) : "r"(addr));
}
__device__ __forceinline__ void cpasync16(unsigned dst, const void* src) {
    asm volatile("cp.async.cg.shared.global [%0], [%1], 16;" :: "r"(dst), "l"(src));
}
__device__ __forceinline__ void cpcommit() { asm volatile("cp.async.commit_group;"); }
__device__ __forceinline__ void cpwait0()  { asm volatile("cp.async.wait_group 0;" ::: "memory"); }

// Stage one chunk's W via cp.async with transpose+swizzle scatter.
// Index math identical to the validated R4 register-store path:
// global [ci][j][n][m16] -> smem [ci][n][j^(n&1)][m16].
__device__ __forceinline__ void stage_W_async(unsigned wbuf, const float* __restrict__ W,
                                              int ch, int tid)
{
    const float* src = W + (size_t)ch * W_FLOATS;
    #pragma unroll
    for (int q = 0; q < 4; q++) {
        const int idx = (tid + q * THREADS) * 4;      // float index, 16B granule
        const int ci = idx >> 10;
        const int r  = idx & 1023;
        const int j  = r >> 7;
        const int n  = (r >> 4) & 7;
        const int m  = r & 15;                        // 0,4,8,12
        const unsigned dst = wbuf +
            (unsigned)((ci << 10) + (n << 7) + (((j ^ (n & 1))) << 4) + m) * 4u;
        cpasync16(dst, src + idx);
    }
}

__global__ __launch_bounds__(THREADS, 1)
void route_kernel(const float* __restrict__ x, const float* __restrict__ W, int stage)
{
    extern __shared__ float sh[];
    float* xs = sh + 2 * W_FLOATS;

    const int tid  = threadIdx.x;
    const int lane = tid & 31;
    const int w    = tid >> 5;
    const int j    = lane >> 2;     // out-cap 0..7
    const int mq   = lane & 3;      // m-quad 0..3
    const int b0   = w * 4;         // warp owns batches b0..b0+3

    // ---- vsum = sum_{st<stage} squash(g_s[st]) for this lane's (4 batches, j, mq) ----
    u64 vp[4][2];
    #pragma unroll
    for (int bb = 0; bb < 4; bb++) {
        float v0 = 0.f, v1 = 0.f, v2v = 0.f, v3 = 0.f;
        for (int st = 0; st < stage; ++st) {
            const float4 s4 = __ldcg(reinterpret_cast<const float4*>(
                &g_s[st][((b0 + bb) * JCAPS + j) * MDIM + mq * 4]));
            float sq = s4.x * s4.x;
            sq = fmaf(s4.y, s4.y, sq);
            sq = fmaf(s4.z, s4.z, sq);
            sq = fmaf(s4.w, s4.w, sq);
            sq += __shfl_xor_sync(0xffffffffu, sq, 1);
            sq += __shfl_xor_sync(0xffffffffu, sq, 2);   // norm^2 over all 16 m
            const float sc = sqrtf(sq) / (1.0f + sq);    // squash scale
            v0 = fmaf(sc, s4.x, v0); v1 = fmaf(sc, s4.y, v1);
            v2v = fmaf(sc, s4.z, v2v); v3 = fmaf(sc, s4.w, v3);
        }
        vp[bb][0] = pk2(v0, v1);
        vp[bb][1] = pk2(v2v, v3);
    }

    u64 sacc[4][2];
    #pragma unroll
    for (int bb = 0; bb < 4; bb++) { sacc[bb][0] = 0ull; sacc[bb][1] = 0ull; }

    const unsigned shbase = (unsigned)__cvta_generic_to_shared(sh);
    const unsigned xsbase = shbase + 2u * W_FLOATS * 4u;
    const unsigned wofs_e = (unsigned)((j * 16) + mq * 4) * 4u;        // even n
    const unsigned wofs_o = (unsigned)(((j ^ 1) * 16) + mq * 4) * 4u;  // odd n (XOR swizzle)

    // ---- double-buffered-W chunk loop ----
    int ch = blockIdx.x;            // < NCHUNKS always (grid <= 512)
    int p  = 0;
    float4 xreg[2];
    stage_W_async(shbase, W, ch, tid);
    cpcommit();
    #pragma unroll
    for (int q = 0; q < 2; q++) {
        const int idx4 = tid + q * THREADS;
        const int b = idx4 >> 4;
        const int k = (idx4 & 15) * 4;
        xreg[q] = __ldcg(reinterpret_cast<const float4*>(
            &x[(size_t)b * (ICAPS * NDIM) + (size_t)ch * (CI * NDIM) + k]));
    }
    bool first = true;

    while (true) {
        if (!first) __syncthreads();   // all warps done reading xs of previous chunk
        cpwait0();                     // this chunk's W has landed (thread-local)
        // store duplicated x for this chunk
        #pragma unroll
        for (int q = 0; q < 2; q++) {
            const int idx4 = tid + q * THREADS;
            const int b = idx4 >> 4;
            const int k = (idx4 & 15) * 4;
            float* d = xs + b * X_STRIDE + 2 * k;
            *reinterpret_cast<float4*>(d)     = make_float4(xreg[q].x, xreg[q].x, xreg[q].y, xreg[q].y);
            *reinterpret_cast<float4*>(d + 4) = make_float4(xreg[q].z, xreg[q].z, xreg[q].w, xreg[q].w);
        }
        __syncthreads();               // W (cross-thread) + x visible to all

        const int chn = ch + (int)gridDim.x;
        const bool have_next = (chn < NCHUNKS);
        if (have_next) {               // prefetch next W into other buffer + next x into regs
            stage_W_async(shbase + (unsigned)(p ^ 1) * (W_FLOATS * 4u), W, chn, tid);
            cpcommit();
            #pragma unroll
            for (int q = 0; q < 2; q++) {
                const int idx4 = tid + q * THREADS;
                const int b = idx4 >> 4;
                const int k = (idx4 & 15) * 4;
                xreg[q] = __ldcg(reinterpret_cast<const float4*>(
                    &x[(size_t)b * (ICAPS * NDIM) + (size_t)chn * (CI * NDIM) + k]));
            }
        }

        // ---- compute this chunk (buffer p) ----
        const unsigned wb = shbase + (unsigned)p * (W_FLOATS * 4u);
        const unsigned we = wb + wofs_e;
        const unsigned wo = wb + wofs_o;

        #pragma unroll 1
        for (int ii = 0; ii < CI; ++ii) {
            u64 wp[8][2];
            #pragma unroll
            for (int n = 0; n < 8; n++) {
                const unsigned a = ((n & 1) ? wo : we) + (unsigned)(ii * 4096 + n * 512);
                lds2(wp[n][0], wp[n][1], a);
            }
            #pragma unroll
            for (int bb = 0; bb < 4; bb++) {
                const unsigned xa = xsbase + (unsigned)((b0 + bb) * X_STRIDE + ii * 16) * 4u;
                u64 xq[8];
                lds2(xq[0], xq[1], xa);          // broadcast loads
                lds2(xq[2], xq[3], xa + 16);
                lds2(xq[4], xq[5], xa + 32);
                lds2(xq[6], xq[7], xa + 48);

                u64 uh0 = mul2(wp[0][0], xq[0]);
                u64 uh1 = mul2(wp[0][1], xq[0]);
                #pragma unroll
                for (int n = 1; n < 8; n++) {
                    fma2(uh0, wp[n][0], xq[n]);
                    fma2(uh1, wp[n][1], xq[n]);
                }
                // logit = dot(vsum, u_hat); |logit| < 1 so no max subtraction
                u64 pp = mul2(uh0, vp[bb][0]);
                fma2(pp, uh1, vp[bb][1]);
                float plo, phi; upk2(pp, plo, phi);
                float pl = plo + phi;
                pl += __shfl_xor_sync(0xffffffffu, pl, 1);
                pl += __shfl_xor_sync(0xffffffffu, pl, 2);
                const float e = __expf(pl);
                float sm = e;
                sm += __shfl_xor_sync(0xffffffffu, sm, 4);
                sm += __shfl_xor_sync(0xffffffffu, sm, 8);
                sm += __shfl_xor_sync(0xffffffffu, sm, 16);
                const float c = __fdividef(e, sm);
                const u64 c2 = pk2(c, c);
                fma2(sacc[bb][0], c2, uh0);
                fma2(sacc[bb][1], c2, uh1);
            }
        }

        if (!have_next) break;
        ch = chn;
        p ^= 1;
        first = false;
    }

    // ---- flush this warp's disjoint (b, j, mq) partials ----
    float* sout = &g_s[stage][0];
    #pragma unroll
    for (int bb = 0; bb < 4; bb++) {
        const int base = ((b0 + bb) * JCAPS + j) * MDIM + mq * 4;
        float a0, a1, a2, a3;
        upk2(sacc[bb][0], a0, a1);
        upk2(sacc[bb][1], a2, a3);
        atomicAdd(&sout[base + 0], a0);
        atomicAdd(&sout[base + 1], a1);
        atomicAdd(&sout[base + 2], a2);
        atomicAdd(&sout[base + 3], a3);
    }
}

// out = squash(s3)
__global__ void final_squash_kernel(float* __restrict__ out)
{
    const int t = blockIdx.x * blockDim.x + threadIdx.x;   // 0..511
    const int b = t >> 3;
    const int j = t & 7;
    const float* sp = &g_s[2][(b * JCAPS + j) * MDIM];
    float sv[MDIM];
    float sn = 0.0f;
    #pragma unroll
    for (int q = 0; q < 4; q++) {
        const float4 tt = __ldcg(reinterpret_cast<const float4*>(sp + q * 4));
        sv[q*4+0] = tt.x; sv[q*4+1] = tt.y; sv[q*4+2] = tt.z; sv[q*4+3] = tt.w;
    }
    #pragma unroll
    for (int m = 0; m < MDIM; m++) sn = fmaf(sv[m], sv[m], sn);
    const float scale = sqrtf(sn) / (1.0f + sn);
    #pragma unroll
    for (int m = 0; m < MDIM; m++) out[(b * JCAPS + j) * MDIM + m] = scale * sv[m];
}

extern "C" void kernel_launch(void* const* d_in, const int* in_sizes, int n_in,
                              void* d_out, int out_size)
{
    const float* x = (const float*)d_in[0];
    const float* W = (const float*)d_in[1];
    if (n_in >= 2 && in_sizes[0] == 8388608 && in_sizes[1] == 4194304) {
        x = (const float*)d_in[1];
        W = (const float*)d_in[0];
    }

    int dev = 0;
    cudaGetDevice(&dev);
    int sm = 148;
    cudaDeviceGetAttribute(&sm, cudaDevAttrMultiProcessorCount, dev);
    if (sm < 1) sm = 1;
    if (sm > 512) sm = 512;

    cudaFuncSetAttribute(route_kernel, cudaFuncAttributeMaxDynamicSharedMemorySize, SMEM_BYTES);

    void* sptr = nullptr;
    cudaGetSymbolAddress(&sptr, g_s);
    cudaMemsetAsync(sptr, 0, sizeof(float) * 3 * BSZ * JCAPS * MDIM);

    for (int st = 0; st < 3; ++st) {
        route_kernel<<<sm, THREADS, SMEM_BYTES>>>(x, W, st);
    }
    final_squash_kernel<<<16, 32>>>((float*)d_out);
}